// round 5
// baseline (speedup 1.0000x reference)
#include <cuda_runtime.h>
#include <stdint.h>

#define B_SZ 16
#define T_SZ 8192
#define H_SZ 256
#define MTOT (B_SZ * T_SZ)   // 131072 rows

// ---------------- helpers ----------------
__device__ __forceinline__ uint32_t smem_u32(const void* p) {
    uint32_t a;
    asm("{ .reg .u64 t; cvta.to.shared.u64 t, %1; cvt.u32.u64 %0, t; }" : "=r"(a) : "l"(p));
    return a;
}

__device__ __forceinline__ uint32_t f2tf32(uint32_t raw) {
    uint32_t r;
    asm("cvt.rna.tf32.f32 %0, %1;" : "=r"(r) : "r"(raw));
    return r;
}

__device__ __forceinline__ void mma_tf32(float* c, const uint32_t* a, const uint32_t* b) {
    asm volatile(
        "mma.sync.aligned.m16n8k8.row.col.f32.tf32.tf32.f32 "
        "{%0,%1,%2,%3}, {%4,%5,%6,%7}, {%8,%9}, {%0,%1,%2,%3};\n"
        : "+f"(c[0]), "+f"(c[1]), "+f"(c[2]), "+f"(c[3])
        : "r"(a[0]), "r"(a[1]), "r"(a[2]), "r"(a[3]), "r"(b[0]), "r"(b[1]));
}

#define CP_ASYNC16(smem, gptr) \
    asm volatile("cp.async.ca.shared.global [%0], [%1], 16;" :: "r"(smem), "l"(gptr) : "memory")
#define CP_COMMIT() asm volatile("cp.async.commit_group;" ::: "memory")
#define CP_WAIT(n)  asm volatile("cp.async.wait_group %0;" :: "n"(n) : "memory")

// ---------------- geometry ----------------
// One CTA: 128 rows x 128 out-cols, BOTH weights (u: warps 0-7, v: warps 8-15).
// grid = (2 col-halves, 1024 row-tiles), 512 threads.
#define NK 16            // k-chunks of BK=16 floats
#define BK 16
#define BKP 20           // padded row stride (words); conflict-free frag LDS
#define MAT_FLOATS (128 * BKP)            // 2560 floats per staged matrix
#define BUF_FLOATS (3 * MAT_FLOATS)       // A, WL, WM
#define BUF_BYTES (BUF_FLOATS * 4)        // 30720
#define EPI_STRIDE 132                    // floats
#define S_U_OFF 0
#define S_V_OFF (128 * EPI_STRIDE * 4)    // 67584
#define EPI_BYTES (S_V_OFF + 136 * EPI_STRIDE * 4)  // 139392
#define DYN_SMEM EPI_BYTES                // > 2*BUF_BYTES = 61440

__global__ __launch_bounds__(512, 1)
void fsmn_fused(const float* __restrict__ X,
                const float* __restrict__ Wlin,
                const float* __restrict__ Wmem,
                const float* __restrict__ blin,
                const float* __restrict__ bmem,
                float* __restrict__ out)
{
    extern __shared__ char smem_raw[];
    const uint32_t sbase = smem_u32(smem_raw);

    const int tid  = threadIdx.x;
    const int wid  = tid >> 5;
    const int lane = tid & 31;
    const int colhalf = blockIdx.x;
    const int rt      = blockIdx.y;
    const int mbase = rt * 128;
    const int nbase = colhalf * 128;

    // warp tiling: 8 warps (per weight) in 2x4 over 128x128
    const int w  = wid & 7;
    const int wm = (w >> 2) * 64;
    const int wn = (w & 3) * 32;
    const int g  = lane >> 2;
    const int cq = lane & 3;

    // staging coords: sr = row 0..127, sc4 = col offset {0,4,8,12}
    const int sr  = tid >> 2;
    const int sc4 = (tid & 3) << 2;
    const uint32_t stOff = (uint32_t)(sr * BKP + sc4) * 4;

    const float* Xrow = X    + (size_t)(mbase + sr) * H_SZ + sc4;
    const float* WLr  = Wlin + (size_t)(nbase + sr) * H_SZ + sc4;
    const float* WMr  = Wmem + (size_t)(nbase + sr) * H_SZ + sc4;

    float acc[4][4][4];
    #pragma unroll
    for (int i = 0; i < 4; i++)
        #pragma unroll
        for (int j = 0; j < 4; j++)
            #pragma unroll
            for (int k = 0; k < 4; k++) acc[i][j][k] = 0.f;

    // ---- prologue: stage chunk 0 ----
    {
        const uint32_t b0 = sbase;
        CP_ASYNC16(b0 + stOff,                    Xrow);
        CP_ASYNC16(b0 + MAT_FLOATS * 4 + stOff,   WLr);
        CP_ASYNC16(b0 + 2 * MAT_FLOATS * 4 + stOff, WMr);
        CP_COMMIT();
    }

    // B-matrix smem base for this warp group (u: WL, v: WM)
    const uint32_t bMatSel = (wid < 8) ? (uint32_t)(MAT_FLOATS * 4)
                                       : (uint32_t)(2 * MAT_FLOATS * 4);

    for (int kt = 0; kt < NK; ++kt) {
        const uint32_t curBuf = sbase + (uint32_t)(kt & 1) * BUF_BYTES;

        if (kt + 1 < NK) {
            const uint32_t nb = sbase + (uint32_t)((kt + 1) & 1) * BUF_BYTES;
            const int ko = (kt + 1) * BK;
            CP_ASYNC16(nb + stOff,                      Xrow + ko);
            CP_ASYNC16(nb + MAT_FLOATS * 4 + stOff,     WLr + ko);
            CP_ASYNC16(nb + 2 * MAT_FLOATS * 4 + stOff, WMr + ko);
            CP_COMMIT();
            CP_WAIT(1);
        } else {
            CP_WAIT(0);
        }
        __syncthreads();

        const uint32_t aBuf = curBuf;
        const uint32_t bBuf = curBuf + bMatSel;

        #pragma unroll
        for (int kk = 0; kk < 2; ++kk) {
            const int c0 = kk * 8 + cq;
            uint32_t af[4][4], bf[4][2];
            #pragma unroll
            for (int mi = 0; mi < 4; ++mi) {
                const int r = wm + mi * 16 + g;
                uint32_t r0, r1, r2, r3;
                asm volatile("ld.shared.b32 %0, [%1];" : "=r"(r0) : "r"(aBuf + (uint32_t)(r * BKP + c0) * 4));
                asm volatile("ld.shared.b32 %0, [%1];" : "=r"(r1) : "r"(aBuf + (uint32_t)((r + 8) * BKP + c0) * 4));
                asm volatile("ld.shared.b32 %0, [%1];" : "=r"(r2) : "r"(aBuf + (uint32_t)(r * BKP + c0 + 4) * 4));
                asm volatile("ld.shared.b32 %0, [%1];" : "=r"(r3) : "r"(aBuf + (uint32_t)((r + 8) * BKP + c0 + 4) * 4));
                af[mi][0] = f2tf32(r0); af[mi][1] = f2tf32(r1);
                af[mi][2] = f2tf32(r2); af[mi][3] = f2tf32(r3);
            }
            #pragma unroll
            for (int ni = 0; ni < 4; ++ni) {
                const int r = wn + ni * 8 + g;
                uint32_t r0, r1;
                asm volatile("ld.shared.b32 %0, [%1];" : "=r"(r0) : "r"(bBuf + (uint32_t)(r * BKP + c0) * 4));
                asm volatile("ld.shared.b32 %0, [%1];" : "=r"(r1) : "r"(bBuf + (uint32_t)(r * BKP + c0 + 4) * 4));
                bf[ni][0] = f2tf32(r0); bf[ni][1] = f2tf32(r1);
            }
            #pragma unroll
            for (int mi = 0; mi < 4; ++mi)
                #pragma unroll
                for (int ni = 0; ni < 4; ++ni)
                    mma_tf32(acc[mi][ni], af[mi], bf[ni]);
        }
        __syncthreads();   // all reads of curBuf done before it is re-staged
    }

    // ================= epilogue (smem reused) =================
    const uint32_t S_U = sbase + S_U_OFF;
    const uint32_t S_V = sbase + S_V_OFF;   // rows 0..7 = halo, 8..135 = tile v

    // stage accumulators: u warps -> S_U rows 0..127 ; v warps -> S_V rows 8..135
    {
        const uint32_t dst = (wid < 8) ? S_U : (S_V + 8u * EPI_STRIDE * 4);
        #pragma unroll
        for (int mi = 0; mi < 4; ++mi) {
            const int r = wm + mi * 16 + g;
            #pragma unroll
            for (int ni = 0; ni < 4; ++ni) {
                const int col = wn + ni * 8 + cq * 2;
                asm volatile("st.shared.v2.b32 [%0], {%1,%2};"
                    :: "r"(dst + (uint32_t)(r * EPI_STRIDE + col) * 4),
                       "r"(__float_as_uint(acc[mi][ni][0])), "r"(__float_as_uint(acc[mi][ni][1])));
                asm volatile("st.shared.v2.b32 [%0], {%1,%2};"
                    :: "r"(dst + (uint32_t)((r + 8) * EPI_STRIDE + col) * 4),
                       "r"(__float_as_uint(acc[mi][ni][2])), "r"(__float_as_uint(acc[mi][ni][3])));
            }
        }
    }

    // halo: v rows mbase-8..mbase-1 (zero for batch-first tiles)
    const bool firstTile = ((rt & 63) == 0);
    #pragma unroll
    for (int pp = 0; pp < 2; ++pp) {
        const int p  = tid + pp * 512;
        const int hr = p >> 7;          // 0..7
        const int c  = p & 127;
        float dot = 0.f;
        if (!firstTile) {
            const float4* xr = (const float4*)(X + (size_t)(mbase - 8 + hr) * H_SZ);
            const float4* wr = (const float4*)(Wmem + (size_t)(nbase + c) * H_SZ);
            float4 s4 = make_float4(0.f, 0.f, 0.f, 0.f);
            #pragma unroll 8
            for (int k4 = 0; k4 < 64; ++k4) {
                float4 a = __ldg(&xr[k4]);
                float4 b = __ldg(&wr[k4]);
                s4.x += a.x * b.x; s4.y += a.y * b.y;
                s4.z += a.z * b.z; s4.w += a.w * b.w;
            }
            dot = (s4.x + s4.y) + (s4.z + s4.w);
        }
        *(float*)((char*)smem_raw + (S_V - sbase) + (uint32_t)(hr * EPI_STRIDE + c) * 4) = dot;
    }
    __syncthreads();

    // window + combine + store. thread: column c, 32-row segment seg.
    {
        const int c   = tid & 127;
        const int seg = tid >> 7;
        const float bias = __ldg(&blin[nbase + c]) + __ldg(&bmem[nbase + c]);
        const float* U = (const float*)((char*)smem_raw + (S_U - sbase));
        const float* V = (const float*)((char*)smem_raw + (S_V - sbase));

        float sum = 0.f;
        #pragma unroll
        for (int j = 0; j < 8; ++j)
            sum += V[(seg * 32 + j) * EPI_STRIDE + c];

        const int t0 = (rt & 63) * 128 + seg * 32;   // batch-local t of first row
        #pragma unroll 4
        for (int i = 0; i < 32; ++i) {
            const int srow = seg * 32 + 8 + i;       // stage-space v row
            sum += V[srow * EPI_STRIDE + c];
            const int tg = t0 + i;
            const float inv = (tg >= 8) ? (1.0f / 9.0f) : (1.0f / (float)(tg + 1));
            const float val = U[(seg * 32 + i) * EPI_STRIDE + c] + sum * inv + bias;
            out[(size_t)(mbase + seg * 32 + i) * H_SZ + nbase + c] = val;
            sum -= V[(srow - 8) * EPI_STRIDE + c];
        }
    }
}

extern "C" void kernel_launch(void* const* d_in, const int* in_sizes, int n_in,
                              void* d_out, int out_size)
{
    const float* x    = (const float*)d_in[0];
    const float* Wlin = (const float*)d_in[1];
    const float* blin = (const float*)d_in[2];
    const float* Wmem = (const float*)d_in[3];
    const float* bmem = (const float*)d_in[4];
    float* out = (float*)d_out;

    static int attr_set = 0;
    if (!attr_set) {
        cudaFuncSetAttribute(fsmn_fused, cudaFuncAttributeMaxDynamicSharedMemorySize, DYN_SMEM);
        attr_set = 1;
    }
    dim3 grid(2, MTOT / 128, 1);
    fsmn_fused<<<grid, 512, DYN_SMEM>>>(x, Wlin, Wmem, blin, bmem, out);
}

// round 8
// speedup vs baseline: 2.4117x; 2.4117x over previous
#include <cuda_runtime.h>
#include <stdint.h>

#define B_SZ 16
#define T_SZ 8192
#define H_SZ 256
#define MTOT (B_SZ * T_SZ)   // 131072 rows

#define NK 16                // k-chunks of 16 floats
#define BKP 20               // padded row stride (words)
#define AROWS 144            // 16 halo/garbage rows + 128 tile rows
#define BROWS 64
#define ABYTES (AROWS * BKP * 4)                 // 11520
#define BLOFF  ABYTES
#define BMOFF  (ABYTES + BROWS * BKP * 4)        // 16640
#define BUFB   (ABYTES + 2 * BROWS * BKP * 4)    // 21760 ; x3 = 65280
#define EPI_STRIDE 68
#define V_OFF  (128 * EPI_STRIDE * 4)            // 34816
#define DYN_SMEM (V_OFF + 136 * EPI_STRIDE * 4)  // 71808 (>= 3*BUFB)

__device__ __forceinline__ uint32_t smem_u32(const void* p) {
    uint32_t a;
    asm("{ .reg .u64 t; cvta.to.shared.u64 t, %1; cvt.u32.u64 %0, t; }" : "=r"(a) : "l"(p));
    return a;
}
__device__ __forceinline__ uint32_t f2tf32(uint32_t raw) {
    uint32_t r;
    asm("cvt.rna.tf32.f32 %0, %1;" : "=r"(r) : "r"(raw));
    return r;
}
__device__ __forceinline__ void mma_tf32(float* c, const uint32_t* a, const uint32_t* b) {
    asm volatile(
        "mma.sync.aligned.m16n8k8.row.col.f32.tf32.tf32.f32 "
        "{%0,%1,%2,%3}, {%4,%5,%6,%7}, {%8,%9}, {%0,%1,%2,%3};\n"
        : "+f"(c[0]), "+f"(c[1]), "+f"(c[2]), "+f"(c[3])
        : "r"(a[0]), "r"(a[1]), "r"(a[2]), "r"(a[3]), "r"(b[0]), "r"(b[1]));
}
#define LDSM_X4(r, addr) \
    asm volatile("ldmatrix.sync.aligned.m8n8.x4.shared.b16 {%0,%1,%2,%3}, [%4];" \
        : "=r"((r)[0]), "=r"((r)[1]), "=r"((r)[2]), "=r"((r)[3]) : "r"(addr))
#define CP_COMMIT() asm volatile("cp.async.commit_group;" ::: "memory")
#define CP_WAIT(n)  asm volatile("cp.async.wait_group %0;" :: "n"(n) : "memory")
#define STS_V2(addr, x, y) \
    asm volatile("st.shared.v2.b32 [%0], {%1,%2};" :: "r"(addr), \
        "r"(__float_as_uint(x)), "r"(__float_as_uint(y)))

// grid (4 col-quarters fastest, 1024 row-tiles), 256 threads, 2 CTAs/SM.
// CTA: out[mbase..+127][nbase..+63], both weights. warps 0-3: u, 4-7: v (+halo).
__global__ __launch_bounds__(256, 2)
void fsmn_fused(const float* __restrict__ X,
                const float* __restrict__ Wlin,
                const float* __restrict__ Wmem,
                const float* __restrict__ blin,
                const float* __restrict__ bmem,
                float* __restrict__ out)
{
    extern __shared__ char smem_raw[];
    const uint32_t sbase = smem_u32(smem_raw);

    const int tid  = threadIdx.x;
    const int wid  = tid >> 5;
    const int lane = tid & 31;
    const int rt    = blockIdx.y;
    const int mbase = rt * 128;
    const int nbase = blockIdx.x * 64;

    const bool isU = (wid < 4);
    const int  w   = wid & 3;
    const int  wm  = (w >> 1) * 64;
    const int  wn  = (w & 1) * 32;
    const int  g   = lane >> 2;
    const int  cq  = lane & 3;

    // ldmatrix per-lane byte offsets (b32 tiles, row stride BKP words)
    const uint32_t aLane = (uint32_t)(((lane & 7) + ((lane >> 3) & 1) * 8) * BKP
                                      + ((lane >> 4) & 1) * 4) * 4;
    // FIX(R7): B addresses must include the warp's n-offset (wn rows).
    const uint32_t bLane = (uint32_t)((wn + (lane & 7) + ((lane >> 4) & 1) * 8) * BKP
                                      + ((lane >> 3) & 1) * 4) * 4;

    // ---- staging slot precompute (5 cp.async slots / thread / k-chunk) ----
    const bool firstB = ((rt & 63) == 0);
    uint32_t st_dst[5]; const float* st_src[5]; uint32_t st_zf[5];
    #pragma unroll
    for (int p = 0; p < 5; ++p) {
        const int idx = tid + p * 256;
        uint32_t dst = 0; const float* src = X; uint32_t zf = 16;
        if (idx < 576) {                       // A: 144 rows x 4 float4
            const int row = idx >> 2, c4 = (idx & 3) * 4;
            dst = (uint32_t)(row * BKP + c4) * 4;
            const bool z = firstB && (row < 16);
            src = z ? X : (X + (size_t)(mbase - 16 + row) * H_SZ + c4);
            zf  = z ? 0u : 16u;
        } else if (idx < 832) {                // Wlin: 64 rows x 4
            const int j = idx - 576, row = j >> 2, c4 = (j & 3) * 4;
            dst = BLOFF + (uint32_t)(row * BKP + c4) * 4;
            src = Wlin + (size_t)(nbase + row) * H_SZ + c4;
        } else if (idx < 1088) {               // Wmem: 64 rows x 4
            const int j = idx - 832, row = j >> 2, c4 = (j & 3) * 4;
            dst = BMOFF + (uint32_t)(row * BKP + c4) * 4;
            src = Wmem + (size_t)(nbase + row) * H_SZ + c4;
        }
        st_dst[p] = dst; st_src[p] = src; st_zf[p] = zf;
    }

#define STAGE(ktv) do {                                                        \
        const uint32_t _db = sbase + (uint32_t)((ktv) % 3) * BUFB;             \
        const int _ko = (ktv) * 16;                                            \
        _Pragma("unroll")                                                      \
        for (int p = 0; p < 5; ++p) {                                          \
            if (p < 4 || tid < 64)                                             \
                asm volatile("cp.async.ca.shared.global [%0], [%1], 16, %2;"   \
                    :: "r"(_db + st_dst[p]), "l"(st_src[p] + _ko),             \
                       "r"(st_zf[p]) : "memory");                              \
        }                                                                      \
        CP_COMMIT();                                                           \
    } while (0)

    float acc[4][4][4];
    #pragma unroll
    for (int i = 0; i < 4; i++)
        #pragma unroll
        for (int j = 0; j < 4; j++)
            #pragma unroll
            for (int k = 0; k < 4; k++) acc[i][j][k] = 0.f;
    float acch[2][4];
    #pragma unroll
    for (int i = 0; i < 2; i++)
        #pragma unroll
        for (int k = 0; k < 4; k++) acch[i][k] = 0.f;

    const uint32_t bSel  = isU ? (uint32_t)BLOFF : (uint32_t)BMOFF;
    const int hbf = (w >> 1) * 2;          // halo b-frag base index (v warps)

    STAGE(0);
    STAGE(1);

    for (int kt = 0; kt < NK; ++kt) {
        if (kt < NK - 1) { CP_WAIT(1); } else { CP_WAIT(0); }
        __syncthreads();
        if (kt + 2 < NK) STAGE(kt + 2);

        const uint32_t Abuf = sbase + (uint32_t)(kt % 3) * BUFB;
        const uint32_t Bbuf = Abuf + bSel;

        #pragma unroll
        for (int kk = 0; kk < 2; ++kk) {
            uint32_t bf[8];
            LDSM_X4(bf,     Bbuf + bLane + (uint32_t)(kk * 8) * 4);
            LDSM_X4(bf + 4, Bbuf + bLane + (uint32_t)(16 * BKP + kk * 8) * 4);
            #pragma unroll
            for (int i = 0; i < 8; ++i) bf[i] = f2tf32(bf[i]);

            #pragma unroll
            for (int mi = 0; mi < 4; ++mi) {
                uint32_t af[4];
                LDSM_X4(af, Abuf + aLane
                            + (uint32_t)((16 + wm + mi * 16) * BKP + kk * 8) * 4);
                #pragma unroll
                for (int i = 0; i < 4; ++i) af[i] = f2tf32(af[i]);
                mma_tf32(acc[mi][0], af, bf + 0);
                mma_tf32(acc[mi][1], af, bf + 2);
                mma_tf32(acc[mi][2], af, bf + 4);
                mma_tf32(acc[mi][3], af, bf + 6);
            }
            if (!isU) {   // halo block: A rows 0..15 (out rows mbase-16..-1)
                uint32_t ah[4];
                LDSM_X4(ah, Abuf + aLane + (uint32_t)(kk * 8) * 4);
                #pragma unroll
                for (int i = 0; i < 4; ++i) ah[i] = f2tf32(ah[i]);
                mma_tf32(acch[0], ah, bf + (hbf + 0) * 2);
                mma_tf32(acch[1], ah, bf + (hbf + 1) * 2);
            }
        }
    }

    // ================= epilogue =================
    __syncthreads();
    {
        const uint32_t sb = sbase + (isU ? 0u : (uint32_t)V_OFF + 8u * EPI_STRIDE * 4);
        #pragma unroll
        for (int mi = 0; mi < 4; ++mi) {
            const int r = wm + mi * 16 + g;
            #pragma unroll
            for (int ni = 0; ni < 4; ++ni) {
                const int col = wn + ni * 8 + cq * 2;
                STS_V2(sb + (uint32_t)(r * EPI_STRIDE + col) * 4,
                       acc[mi][ni][0], acc[mi][ni][1]);
                STS_V2(sb + (uint32_t)((r + 8) * EPI_STRIDE + col) * 4,
                       acc[mi][ni][2], acc[mi][ni][3]);
            }
        }
        if (!isU) {   // halo rows: keep upper half (out rows -8..-1) -> V rows g
            const int hb = (w & 1) * 32 + (w >> 1) * 16;
            #pragma unroll
            for (int nil = 0; nil < 2; ++nil) {
                const int col = hb + nil * 8 + cq * 2;
                STS_V2(sbase + (uint32_t)V_OFF + (uint32_t)(g * EPI_STRIDE + col) * 4,
                       acch[nil][2], acch[nil][3]);
            }
        }
    }
    __syncthreads();

    // window + combine + store.  U[R][c] = u, V[vr][c] = v[out-row vr-8].
    {
        const int c   = tid & 63;
        const int seg = tid >> 6;
        const float bias = __ldg(&blin[nbase + c]) + __ldg(&bmem[nbase + c]);
        const float* U = (const float*)smem_raw;
        const float* V = (const float*)(smem_raw + V_OFF);

        float sum = 0.f;
        #pragma unroll
        for (int j = 0; j < 8; ++j)
            sum += V[(seg * 32 + j) * EPI_STRIDE + c];

        const int tloc0 = (rt & 63) * 128 + seg * 32;
        #pragma unroll 4
        for (int i = 0; i < 32; ++i) {
            const int R = seg * 32 + i;
            sum += V[(R + 8) * EPI_STRIDE + c];
            const int t = tloc0 + i;
            const float inv = (t >= 8) ? (1.0f / 9.0f) : (1.0f / (float)(t + 1));
            out[(size_t)(mbase + R) * H_SZ + nbase + c] =
                U[R * EPI_STRIDE + c] + sum * inv + bias;
            sum -= V[R * EPI_STRIDE + c];
        }
    }
#undef STAGE
}

extern "C" void kernel_launch(void* const* d_in, const int* in_sizes, int n_in,
                              void* d_out, int out_size)
{
    const float* x    = (const float*)d_in[0];
    const float* Wlin = (const float*)d_in[1];
    const float* blin = (const float*)d_in[2];
    const float* Wmem = (const float*)d_in[3];
    const float* bmem = (const float*)d_in[4];
    float* out = (float*)d_out;

    static int attr_set = 0;
    if (!attr_set) {
        cudaFuncSetAttribute(fsmn_fused, cudaFuncAttributeMaxDynamicSharedMemorySize, DYN_SMEM);
        attr_set = 1;
    }
    dim3 grid(4, MTOT / 128, 1);   // col-quarter fastest -> x tile L2 reuse
    fsmn_fused<<<grid, 256, DYN_SMEM>>>(x, Wlin, Wmem, blin, bmem, out);
}